// round 17
// baseline (speedup 1.0000x reference)
#include <cuda_runtime.h>
#include <cuda_bf16.h>
#include <cstdint>

// Problem constants (fixed by the reference): N=100000, M=8, K=256, D=64
#define PQ_N 100000
#define PQ_M 8
#define PQ_K 256
#define PQ_D 64
#define NTILE 384          // n-rows per block
#define THREADS 384        // 12 warps: (w>>2) row-block of 128, (w&3) k-quarter
#define FLT_BIG 3.402823466e38f

// ---------------- packed f32x2 helpers ----------------
__device__ __forceinline__ unsigned long long pack2(float a) {
    unsigned long long r;
    asm("mov.b64 %0, {%1, %1};" : "=l"(r) : "f"(a));
    return r;
}
__device__ __forceinline__ void ffma2(unsigned long long &d,
                                      unsigned long long a,
                                      unsigned long long b) {
    asm("fma.rn.f32x2 %0, %1, %2, %0;" : "+l"(d) : "l"(a), "l"(b));
}
__device__ __forceinline__ float2 unpack2(unsigned long long v) {
    float2 f;
    asm("mov.b64 {%0, %1}, %2;" : "=f"(f.x), "=f"(f.y) : "l"(v));
    return f;
}

// NEON/LLVM-emulated sum of squares (frozen: matches reference c_sq / x_sq)
__device__ __forceinline__ float neon_sumsq64(const float* v) {
    float a0[4] = {0.f,0.f,0.f,0.f}, a1[4] = {0.f,0.f,0.f,0.f};
    #pragma unroll
    for (int i = 0; i < 8; ++i) {
        #pragma unroll
        for (int l = 0; l < 4; ++l) {
            a0[l] = __fadd_rn(a0[l], __fmul_rn(v[8*i+l],   v[8*i+l]));
            a1[l] = __fadd_rn(a1[l], __fmul_rn(v[8*i+4+l], v[8*i+4+l]));
        }
    }
    float s0 = __fadd_rn(a0[0],a1[0]), s1 = __fadd_rn(a0[1],a1[1]);
    float s2 = __fadd_rn(a0[2],a1[2]), s3 = __fadd_rn(a0[3],a1[3]);
    return __fadd_rn(__fadd_rn(s0,s1), __fadd_rn(s2,s3));
}

// smem layout (floats):
//   cs    [64][256]      transposed codebook                  16384
//   xs    [64][NTILE]    transposed x tile, PRE-NEGATED       24576
//   csq   [256]          ||c_k||^2 (NEON order)                 256
//   scsq  [256]          0.5*||c_k||^2 (acc init)               256
//   xsqs  [NTILE]        ||x_n||^2 (NEON order)                 384
//   mrgf  [4][NTILE][2]  per-quarter (m1, m2)                  3072
//   mrgi  [4][NTILE][2]  per-quarter (i1, i2) as int16         1536
#define SM_CS    0
#define SM_XS    (64 * 256)
#define SM_CSQ   (SM_XS + 64 * NTILE)
#define SM_SCSQ  (SM_CSQ + 256)
#define SM_XSQ   (SM_SCSQ + 256)
#define SM_MRGF  (SM_XSQ + NTILE)
#define SM_MRGI  (SM_MRGF + 4 * NTILE * 2)
#define SM_FLOATS (SM_MRGI + 4 * NTILE)   // int16 merge ids: 4*NTILE*2 shorts

extern "C" __global__ void __launch_bounds__(THREADS, 1)
pq_q4p_kernel(const float* __restrict__ x,
              const float* __restrict__ cb,
              float* __restrict__ qout,
              float* __restrict__ idf,
              long long* __restrict__ idl,
              int id_mode)
{
    extern __shared__ float smem[];
    float* cs   = smem + SM_CS;
    float* xs   = smem + SM_XS;
    float* csq  = smem + SM_CSQ;
    float* scsq = smem + SM_SCSQ;
    float* xsqs = smem + SM_XSQ;
    float* mrgf = smem + SM_MRGF;
    short* mrgi = reinterpret_cast<short*>(smem + SM_MRGI);

    const int tid  = threadIdx.x;
    const int w    = tid >> 5;
    const int lane = tid & 31;
    const int m    = blockIdx.y;
    const int n0   = blockIdx.x * NTILE;
    const float* cbm = cb + (size_t)m * PQ_K * PQ_D;

    // ---- stage codebook (tid<256): transposed cs; NEON csq; 0.5*csq ----
    if (tid < 256) {
        const float4* src = reinterpret_cast<const float4*>(cbm + (size_t)tid * PQ_D);
        float cw[64];
        #pragma unroll
        for (int d4 = 0; d4 < 16; ++d4) {
            float4 v = src[d4];
            int d = d4 * 4;
            cw[d+0]=v.x; cw[d+1]=v.y; cw[d+2]=v.z; cw[d+3]=v.w;
            cs[(d+0)*256 + tid] = v.x;
            cs[(d+1)*256 + tid] = v.y;
            cs[(d+2)*256 + tid] = v.z;
            cs[(d+3)*256 + tid] = v.w;
        }
        float sq = neon_sumsq64(cw);
        csq[tid]  = sq;
        scsq[tid] = 0.5f * sq;   // exact power-of-two scale
    }

    // ---- stage x row tid: transposed + PRE-NEGATED; NEON xsq ----
    {
        const int n = n0 + tid;
        float xw[64];
        if (n < PQ_N) {
            const float4* gx = reinterpret_cast<const float4*>(
                x + (size_t)n * (PQ_M * PQ_D) + (size_t)m * PQ_D);
            #pragma unroll
            for (int d4 = 0; d4 < 16; ++d4) {
                float4 v = gx[d4];
                xw[d4*4+0]=v.x; xw[d4*4+1]=v.y; xw[d4*4+2]=v.z; xw[d4*4+3]=v.w;
            }
        } else {
            #pragma unroll
            for (int d = 0; d < 64; ++d) xw[d] = 0.f;
        }
        #pragma unroll
        for (int d = 0; d < 64; ++d) xs[d * NTILE + tid] = -xw[d];
        xsqs[tid] = neon_sumsq64(xw);   // sign-invariant
    }
    __syncthreads();

    // ---- FAST PASS: warp (w>>2) owns rows (w>>2)*128 + 4*lane + {0..3};
    //      k-quarter = (w&3)*64. Chain: acc = 0.5*csq + sum_d (-x_d)*c_d,
    //      d ascending, fused — bit-identical to the R6/R15-verified pass.
    //      Explicit d+1 prefetch (regs available at 384 thr). ----
    const int kbase = (w & 3) * 64;
    const int rb    = (w >> 2) * 128 + 4 * lane;   // first of 4 rows

    float m1r[4] = {FLT_BIG, FLT_BIG, FLT_BIG, FLT_BIG};
    float m2r[4] = {FLT_BIG, FLT_BIG, FLT_BIG, FLT_BIG};
    int   i1r[4] = {0,0,0,0}, i2r[4] = {0,0,0,0};

    #pragma unroll 1
    for (int kc = 0; kc < 64; kc += 16) {     // 4 chunks of 8 k-pairs
        unsigned long long acc[4][8];
        {
            const unsigned long long* q0 =
                reinterpret_cast<const unsigned long long*>(scsq + kbase + kc);
            #pragma unroll
            for (int j = 0; j < 8; ++j) {
                unsigned long long q = q0[j];
                acc[0][j] = q; acc[1][j] = q; acc[2][j] = q; acc[3][j] = q;
            }
        }

        const float* xp      = xs + rb;
        const ulonglong2* cp = reinterpret_cast<const ulonglong2*>(cs + kbase + kc);

        // software pipeline: prefetch d+1 while consuming d
        float4 xv = *reinterpret_cast<const float4*>(xp);
        ulonglong2 ca = cp[0], cb2 = cp[1], cc = cp[2], cd = cp[3];

        #pragma unroll 4
        for (int d = 0; d < 64; ++d) {
            float4 xv_n;
            ulonglong2 ca_n, cb_n, cc_n, cd_n;
            if (d < 63) {
                xp += NTILE;
                cp += 64;   // one cs row = 256 floats = 1024 B = 64 ulonglong2
                xv_n = *reinterpret_cast<const float4*>(xp);
                ca_n = cp[0]; cb_n = cp[1]; cc_n = cp[2]; cd_n = cp[3];
            }
            unsigned long long x0 = pack2(xv.x);   // already -x
            unsigned long long x1 = pack2(xv.y);
            unsigned long long x2 = pack2(xv.z);
            unsigned long long x3 = pack2(xv.w);
            ffma2(acc[0][0], x0, ca.x);  ffma2(acc[0][1], x0, ca.y);
            ffma2(acc[1][0], x1, ca.x);  ffma2(acc[1][1], x1, ca.y);
            ffma2(acc[2][0], x2, ca.x);  ffma2(acc[2][1], x2, ca.y);
            ffma2(acc[3][0], x3, ca.x);  ffma2(acc[3][1], x3, ca.y);
            ffma2(acc[0][2], x0, cb2.x); ffma2(acc[0][3], x0, cb2.y);
            ffma2(acc[1][2], x1, cb2.x); ffma2(acc[1][3], x1, cb2.y);
            ffma2(acc[2][2], x2, cb2.x); ffma2(acc[2][3], x2, cb2.y);
            ffma2(acc[3][2], x3, cb2.x); ffma2(acc[3][3], x3, cb2.y);
            ffma2(acc[0][4], x0, cc.x);  ffma2(acc[0][5], x0, cc.y);
            ffma2(acc[1][4], x1, cc.x);  ffma2(acc[1][5], x1, cc.y);
            ffma2(acc[2][4], x2, cc.x);  ffma2(acc[2][5], x2, cc.y);
            ffma2(acc[3][4], x3, cc.x);  ffma2(acc[3][5], x3, cc.y);
            ffma2(acc[0][6], x0, cd.x);  ffma2(acc[0][7], x0, cd.y);
            ffma2(acc[1][6], x1, cd.x);  ffma2(acc[1][7], x1, cd.y);
            ffma2(acc[2][6], x2, cd.x);  ffma2(acc[2][7], x2, cd.y);
            ffma2(acc[3][6], x3, cd.x);  ffma2(acc[3][7], x3, cd.y);
            if (d < 63) {
                xv = xv_n; ca = ca_n; cb2 = cb_n; cc = cc_n; cd = cd_n;
            }
        }

        // running top-2 per row, ascending k (strict <)
        #pragma unroll
        for (int r = 0; r < 4; ++r) {
            #pragma unroll
            for (int j = 0; j < 8; ++j) {
                float2 s = unpack2(acc[r][j]);
                const int k0 = kbase + kc + 2*j;
                if (s.x < m1r[r])      { m2r[r]=m1r[r]; i2r[r]=i1r[r]; m1r[r]=s.x; i1r[r]=k0; }
                else if (s.x < m2r[r]) { m2r[r]=s.x; i2r[r]=k0; }
                if (s.y < m1r[r])      { m2r[r]=m1r[r]; i2r[r]=i1r[r]; m1r[r]=s.y; i1r[r]=k0+1; }
                else if (s.y < m2r[r]) { m2r[r]=s.y; i2r[r]=k0+1; }
            }
        }
    }

    // ---- publish per-quarter top-2 (each row owned by 1 thread/quarter) ----
    const int quarter = w & 3;
    #pragma unroll
    for (int r = 0; r < 4; ++r) {
        const int row = rb + r;
        mrgf[(quarter * NTILE + row) * 2 + 0] = m1r[r];
        mrgf[(quarter * NTILE + row) * 2 + 1] = m2r[r];
        mrgi[(quarter * NTILE + row) * 2 + 0] = (short)i1r[r];
        mrgi[(quarter * NTILE + row) * 2 + 1] = (short)i2r[r];
    }
    __syncthreads();

    // ---- merge + frozen H1 refine + write: thread tid owns row tid ----
    {
        const int row = tid;
        const int n   = n0 + row;

        // sequential merge of 4 k-ordered sorted pairs (verified R15 logic);
        // strict < keeps ties at the lower k.
        float best   = mrgf[(0 * NTILE + row) * 2 + 0];
        float second = mrgf[(0 * NTILE + row) * 2 + 1];
        int   ibest  = mrgi[(0 * NTILE + row) * 2 + 0];
        int   isec   = mrgi[(0 * NTILE + row) * 2 + 1];
        #pragma unroll
        for (int q = 1; q < 4; ++q) {
            const float b1 = mrgf[(q * NTILE + row) * 2 + 0];
            const float b2 = mrgf[(q * NTILE + row) * 2 + 1];
            const int  ib1 = mrgi[(q * NTILE + row) * 2 + 0];
            const int  ib2 = mrgi[(q * NTILE + row) * 2 + 1];
            if (b1 < best) {
                if (b2 < best) { second = b2;   isec = ib2; }
                else           { second = best; isec = ibest; }  // tie -> lower k
                best = b1; ibest = ib1;
            } else if (b1 < second) { second = b1; isec = ib1; }
        }

        // FROZEN H1 refinement (verified exact vs reference): dot = separate
        // rn-mul + rn-add chain over d ascending; dist left-assoc; tie ->
        // lower k. Score-gap 0.75e-3 == dist-gap 1.5e-3 window.
        if (n < PQ_N && (second - best < 0.75e-3f)) {
            const float* xg = x + (size_t)n * (PQ_M * PQ_D) + (size_t)m * PQ_D;
            float ea = 0.f, eb = 0.f;
            #pragma unroll 4
            for (int d = 0; d < 64; ++d) {
                float xv = xg[d];
                ea = __fadd_rn(ea, __fmul_rn(xv, cs[d*256 + ibest]));
                eb = __fadd_rn(eb, __fmul_rn(xv, cs[d*256 + isec]));
            }
            const float xsq = xsqs[row];
            float da = __fadd_rn(__fsub_rn(xsq, __fmul_rn(2.0f, ea)), csq[ibest]);
            float db = __fadd_rn(__fsub_rn(xsq, __fmul_rn(2.0f, eb)), csq[isec]);
            if (db < da || (db == da && isec < ibest)) ibest = isec;
        }

        if (n < PQ_N) {
            // write Q row (selected codeword) from transposed cs
            float* qrow = qout + (size_t)n * (PQ_M * PQ_D) + (size_t)m * PQ_D;
            #pragma unroll
            for (int d4 = 0; d4 < 16; ++d4) {
                float4 v;
                v.x = cs[(d4*4 + 0)*256 + ibest];
                v.y = cs[(d4*4 + 1)*256 + ibest];
                v.z = cs[(d4*4 + 2)*256 + ibest];
                v.w = cs[(d4*4 + 3)*256 + ibest];
                reinterpret_cast<float4*>(qrow)[d4] = v;
            }
            if (id_mode == 1)      idf[(size_t)m * PQ_N + n] = (float)ibest;
            else if (id_mode == 2) idl[(size_t)m * PQ_N + n] = (long long)ibest;
        }
    }
}

extern "C" void kernel_launch(void* const* d_in, const int* in_sizes, int n_in,
                              void* d_out, int out_size) {
    const float* x  = (const float*)d_in[0];   // (N, 512) f32
    const float* cb = (const float*)d_in[1];   // (8, 256, 64) f32

    float* out = (float*)d_out;
    const long long QN  = (long long)PQ_N * PQ_M * PQ_D;  // 51,200,000
    const long long IDN = (long long)PQ_M * PQ_N;         // 800,000

    int id_mode = 0;
    float* idf = nullptr;
    long long* idl = nullptr;
    long long osz = (long long)out_size;
    if (osz >= QN + 2 * IDN) {
        id_mode = 2;
        idl = reinterpret_cast<long long*>(out + QN);
    } else if (osz >= QN + IDN) {
        id_mode = 1;
        idf = out + QN;
    }

    const int smem_bytes = SM_FLOATS * sizeof(float);  // ~187KB
    cudaFuncSetAttribute(pq_q4p_kernel,
                         cudaFuncAttributeMaxDynamicSharedMemorySize, smem_bytes);

    dim3 grid((PQ_N + NTILE - 1) / NTILE, PQ_M);
    pq_q4p_kernel<<<grid, THREADS, smem_bytes>>>(x, cb, out, idf, idl, id_mode);
}